// round 11
// baseline (speedup 1.0000x reference)
#include <cuda_runtime.h>
#include <cstdint>

#define D_MODEL 512
#define KEY_DIM 128
#define BS_N 16
#define CTX_PER 1024
#define ARGS_PER 32
#define N_ARGS (BS_N * ARGS_PER)      /* 512  */
#define N_CTX  (BS_N * CTX_PER)       /* 16384 */
#define P_TOT  (N_ARGS * CTX_PER)     /* 524288 */

// Scratch (allocation-free rule: device globals). Accessed ONLY from device
// code -- host-side references give the host shadow symbol (R3 bug).
// g_Qp holds TF32-ROUNDED values so logits-A needs no cvt.
__device__ float g_Qp[N_ARGS * D_MODEL];
__device__ float g_qb[N_ARGS];

// ---------------------------------------------------------------------------
__device__ __forceinline__ uint32_t f2tf32(float f) {
    uint32_t r;
    asm("cvt.rna.tf32.f32 %0, %1;" : "=r"(r) : "f"(f));
    return r;
}
__device__ __forceinline__ uint32_t bits2tf32(uint32_t b) {
    return f2tf32(__uint_as_float(b));
}

__device__ __forceinline__ void mma_tf32(float (&d)[4], const uint32_t (&a)[4],
                                         uint32_t b0, uint32_t b1) {
    asm volatile(
        "mma.sync.aligned.m16n8k8.row.col.f32.tf32.tf32.f32 "
        "{%0,%1,%2,%3}, {%4,%5,%6,%7}, {%8,%9}, {%0,%1,%2,%3};"
        : "+f"(d[0]), "+f"(d[1]), "+f"(d[2]), "+f"(d[3])
        : "r"(a[0]), "r"(a[1]), "r"(a[2]), "r"(a[3]), "r"(b0), "r"(b1));
}

__device__ __forceinline__ void ldsm_x4(uint32_t (&r)[4], uint32_t addr) {
    asm volatile(
        "ldmatrix.sync.aligned.m8n8.x4.shared.b16 {%0,%1,%2,%3}, [%4];"
        : "=r"(r[0]), "=r"(r[1]), "=r"(r[2]), "=r"(r[3]) : "r"(addr));
}

__device__ __forceinline__ uint32_t s2u(const void* p) {
    return (uint32_t)__cvta_generic_to_shared(p);
}
__device__ __forceinline__ void cp16(uint32_t smem_addr, const void* gmem) {
    asm volatile("cp.async.cg.shared.global [%0], [%1], 16;"
                 :: "r"(smem_addr), "l"(gmem));
}
__device__ __forceinline__ void cp_commit() {
    asm volatile("cp.async.commit_group;");
}
template<int N> __device__ __forceinline__ void cp_wait() {
    asm volatile("cp.async.wait_group %0;" :: "n"(N));
}

// ---------------------------------------------------------------------------
// Tensor-core GEMM: D[32 x 64] tile of Qrows[32,KD] @ Crows[64,KD]^T
//   256 threads = 8 warps as 2(m) x 4(n). S-stage cp.async pipeline
//   (stage = 32 k, 12 KB); inner loop unrolled x S so every stage slot is a
//   compile-time immediate (no dynamic reg-array indexing -- R9 trap).
//   wait_group<S-2> keeps (S-2)*12 KB per CTA outstanding -> MLP for DRAM.
//   XOR-swizzled 128B rows -> conflict-free LDSM.
// LOGITS (S=8): A (g_Qp) pre-rounded tf32 -> no cvt on A; C: 4 cvts/kk.
// !LOGITS/qp (S=4): cvts both operands; stores tf32-rounded g_Qp; computes
//   g_qb on blockIdx.x==0; also fills the rows output plane (input-free,
//   uses this kernel's idle bandwidth).
// ---------------------------------------------------------------------------
template<int KD, int S, bool LOGITS>
__global__ __launch_bounds__(256, 2) void gemm_tc(const float* __restrict__ Qm,
                                                  const float* __restrict__ Cm,
                                                  const float* __restrict__ bv,
                                                  float* __restrict__ out,
                                                  float* __restrict__ rows_out) {
    constexpr int NST  = KD / 32;                   // total k-stages of work
    static_assert(NST % S == 0, "NST must be a multiple of S");
    constexpr int OSTR = LOGITS ? CTX_PER : D_MODEL;
    constexpr uint32_t QSTG = 32 * 32 * 4;          // 4 KB per Q stage
    constexpr uint32_t CSTG = 64 * 32 * 4;          // 8 KB per C stage

    __shared__ float Qs[S * 32 * 32];
    __shared__ float Cs[S * 64 * 32];

    const int tid  = threadIdx.x;
    const int lane = tid & 31;
    const int warp = tid >> 5;
    const int wm   = warp >> 2;
    const int wn   = warp & 3;
    const int qr   = lane >> 2;
    const int qc   = lane & 3;

    const float* Qbase = LOGITS ? (const float*)g_Qp : Qm;
    const int qrow_base = blockIdx.y * 32;
    const int crow_base = (LOGITS ? blockIdx.y * CTX_PER : 0) + blockIdx.x * 64;
    const int ocol_base = blockIdx.x * 64;

    const uint32_t QsU = s2u(Qs);
    const uint32_t CsU = s2u(Cs);

    // ---- loader offsets (bytes within a stage)
    const int lq_row = tid >> 3;
    const int lq_seg = tid & 7;
    const float* qsrc = Qbase + (size_t)(qrow_base + lq_row) * KD + lq_seg * 4;
    const uint32_t qoff = (uint32_t)(lq_row * 32 + (lq_seg ^ (lq_row & 7)) * 4) * 4;

    const int lc_row0 = tid >> 3;                   // 0..31
    const int lc_row1 = lc_row0 + 32;               // 32..63
    const float* csrc0 = Cm + (size_t)(crow_base + lc_row0) * KD + lq_seg * 4;
    const float* csrc1 = Cm + (size_t)(crow_base + lc_row1) * KD + lq_seg * 4;
    const uint32_t coff0 = (uint32_t)(lc_row0 * 32 + (lq_seg ^ (lc_row0 & 7)) * 4) * 4;
    const uint32_t coff1 = (uint32_t)(lc_row1 * 32 + (lq_seg ^ (lc_row1 & 7)) * 4) * 4;

    // ---- LDSM per-kk byte offsets (unrolled kk => constant regs)
    const int arow  = 16 * wm + (lane & 15);
    const int ahi   = lane >> 4;
    const int amask = arow & 7;
    const int brow  = 16 * wn + (lane & 15);
    const int bmask = brow & 7;
    uint32_t aoff[4], boff[4];
    #pragma unroll
    for (int kk = 0; kk < 4; kk++) {
        aoff[kk] = (uint32_t)(arow * 128 + (((kk * 2 + ahi) ^ amask) * 16));
        boff[kk] = (uint32_t)(brow * 128 + (((kk * 2 + ahi) ^ bmask) * 16));
    }

    float acc[2][4] = {};

    // ---- prologue: issue stages 0..S-2 (slots are literals)
    #pragma unroll
    for (int s = 0; s < S - 1; s++) {
        cp16(QsU + s * QSTG + qoff, qsrc + s * 32);
        cp16(CsU + s * CSTG + coff0, csrc0 + s * 32);
        cp16(CsU + s * CSTG + coff1, csrc1 + s * 32);
        cp_commit();
    }

    // ---- main loop: inner unroll x S keeps stage slot compile-time
    #pragma unroll 1
    for (int itS = 0; itS < NST / S; itS++) {
        #pragma unroll
        for (int s = 0; s < S; s++) {
            const int st = itS * S + s;
            cp_wait<S - 2>();
            __syncthreads();

            const uint32_t qstage = QsU + s * QSTG;
            const uint32_t cstage = CsU + s * CSTG;
            #pragma unroll
            for (int kk = 0; kk < 4; kk++) {
                uint32_t a[4], bt[4];
                ldsm_x4(a, qstage + aoff[kk]);
                ldsm_x4(bt, cstage + boff[kk]);
                if (!LOGITS) {
                    #pragma unroll
                    for (int u = 0; u < 4; u++) a[u] = bits2tf32(a[u]);
                }
                #pragma unroll
                for (int u = 0; u < 4; u++) bt[u] = bits2tf32(bt[u]);
                mma_tf32(acc[0], a, bt[0], bt[2]);
                mma_tf32(acc[1], a, bt[1], bt[3]);
            }

            if (st + S - 1 < NST) {
                const int nb = (s + S - 1) & (S - 1); // compile-time slot
                const int ks = (st + S - 1) * 32;
                cp16(QsU + nb * QSTG + qoff, qsrc + ks);
                cp16(CsU + nb * CSTG + coff0, csrc0 + ks);
                cp16(CsU + nb * CSTG + coff1, csrc1 + ks);
            }
            cp_commit();
        }
    }

    // ---- epilogue: warp tile rows [16wm,16wm+16), cols [16wn,16wn+16)
    #pragma unroll
    for (int nt = 0; nt < 2; nt++) {
        #pragma unroll
        for (int half = 0; half < 2; half++) {
            const int rg = qrow_base + 16 * wm + qr + half * 8;
            const int col = ocol_base + 16 * wn + nt * 8 + qc * 2;
            const size_t off = (size_t)rg * OSTR + col;
            float v0 = acc[nt][half * 2 + 0];
            float v1 = acc[nt][half * 2 + 1];
            if (LOGITS) {
                const float qb = g_qb[rg];
                *(float2*)(out + off) = make_float2(v0 + qb, v1 + qb);
            } else {
                *(float2*)(g_Qp + off) =
                    make_float2(__uint_as_float(f2tf32(v0)),
                                __uint_as_float(f2tf32(v1)));
            }
        }
    }

    if (!LOGITS) {
        // ---- fill rows output plane: rows[p] = p >> 10 (input-free work,
        // distributed across this kernel's 128 CTAs: 4096 floats each)
        if (rows_out) {
            const int cta = blockIdx.y * gridDim.x + blockIdx.x;  // 0..127
            const int base = cta * 4096;
            float* dst = rows_out + base;
            #pragma unroll
            for (int i = 0; i < 4; i++) {
                int idx = tid * 4 + i * 1024;
                float fr = (float)((base + idx) >> 10);
                *(float4*)(dst + idx) = make_float4(fr, fr, fr, fr);
            }
        }
        // ---- fused qb (one column of blocks)
        if (blockIdx.x == 0 && tid < 128) {
            const int row = qrow_base + (tid >> 2);
            const int seg = tid & 3;
            const float* ap = Qm + (size_t)row * KEY_DIM + seg * 32;
            const float* bp = bv + seg * 32;
            float s = 0.f;
            #pragma unroll
            for (int k = 0; k < 8; k++) {
                float4 a  = *(const float4*)(ap + 4 * k);
                float4 bb = *(const float4*)(bp + 4 * k);
                s = fmaf(a.x, bb.x, s); s = fmaf(a.y, bb.y, s);
                s = fmaf(a.z, bb.z, s); s = fmaf(a.w, bb.w, s);
            }
            s += __shfl_xor_sync(0xffffffffu, s, 1);
            s += __shfl_xor_sync(0xffffffffu, s, 2);
            if (seg == 0) g_qb[row] = s;
        }
    }
}

// ---------------------------------------------------------------------------
extern "C" void kernel_launch(void* const* d_in, const int* in_sizes, int n_in,
                              void* d_out, int out_size) {
    const float* argv = nullptr;
    const float* ctxv = nullptr;
    const float* Wm   = nullptr;
    const float* bv   = nullptr;
    int seen_65536 = 0;
    for (int i = 0; i < n_in; i++) {
        long sz = in_sizes[i];
        if (sz == (long)N_CTX * D_MODEL) {
            ctxv = (const float*)d_in[i];
        } else if (sz == (long)N_ARGS * KEY_DIM) {   // == D_MODEL*KEY_DIM too
            if (seen_65536++ == 0) argv = (const float*)d_in[i];
            else                   Wm   = (const float*)d_in[i];
        } else if (sz == KEY_DIM) {
            bv = (const float*)d_in[i];
        }
    }

    float* out        = (float*)d_out;
    float* rows_out   = nullptr;
    float* logits_out = out;
    if (out_size >= 2 * P_TOT) {        // (rows, logits) concatenated
        rows_out   = out;
        logits_out = out + P_TOT;
    }

    // Qp = arg @ W^T (+ qb + rows plane), S=4, K=128
    gemm_tc<KEY_DIM, 4, false><<<dim3(8, 16), 256>>>(argv, Wm, bv,
                                                     nullptr, rows_out);

    // logits: per state: [32,1024] = Qp_s @ C_s^T + qb, S=8, K=512
    gemm_tc<D_MODEL, 8, true><<<dim3(16, 16), 256>>>(nullptr, ctxv, nullptr,
                                                     logits_out, nullptr);
}

// round 12
// speedup vs baseline: 1.1380x; 1.1380x over previous
#include <cuda_runtime.h>
#include <cstdint>

#define D_MODEL 512
#define KEY_DIM 128
#define BS_N 16
#define CTX_PER 1024
#define ARGS_PER 32
#define N_ARGS (BS_N * ARGS_PER)      /* 512  */
#define N_CTX  (BS_N * CTX_PER)       /* 16384 */
#define P_TOT  (N_ARGS * CTX_PER)     /* 524288 */

// Scratch (allocation-free rule: device globals). Device-side access only
// (host-side reference = host shadow symbol, the R3 bug).
// g_Qp holds TF32-ROUNDED values so logits-A needs no cvt.
__device__ float g_Qp[N_ARGS * D_MODEL];
__device__ float g_qb[N_ARGS];

// ---------------------------------------------------------------------------
__device__ __forceinline__ uint32_t f2tf32(float f) {
    uint32_t r;
    asm("cvt.rna.tf32.f32 %0, %1;" : "=r"(r) : "f"(f));
    return r;
}
__device__ __forceinline__ uint32_t bits2tf32(uint32_t b) {
    return f2tf32(__uint_as_float(b));
}

__device__ __forceinline__ void mma_tf32(float (&d)[4], const uint32_t (&a)[4],
                                         uint32_t b0, uint32_t b1) {
    asm volatile(
        "mma.sync.aligned.m16n8k8.row.col.f32.tf32.tf32.f32 "
        "{%0,%1,%2,%3}, {%4,%5,%6,%7}, {%8,%9}, {%0,%1,%2,%3};"
        : "+f"(d[0]), "+f"(d[1]), "+f"(d[2]), "+f"(d[3])
        : "r"(a[0]), "r"(a[1]), "r"(a[2]), "r"(a[3]), "r"(b0), "r"(b1));
}

__device__ __forceinline__ void ldsm_x4(uint32_t (&r)[4], uint32_t addr) {
    asm volatile(
        "ldmatrix.sync.aligned.m8n8.x4.shared.b16 {%0,%1,%2,%3}, [%4];"
        : "=r"(r[0]), "=r"(r[1]), "=r"(r[2]), "=r"(r[3]) : "r"(addr));
}

__device__ __forceinline__ uint32_t s2u(const void* p) {
    return (uint32_t)__cvta_generic_to_shared(p);
}
__device__ __forceinline__ void cp16(uint32_t smem_addr, const void* gmem) {
    asm volatile("cp.async.cg.shared.global [%0], [%1], 16;"
                 :: "r"(smem_addr), "l"(gmem));
}
__device__ __forceinline__ void cp_commit() {
    asm volatile("cp.async.commit_group;");
}
template<int N> __device__ __forceinline__ void cp_wait() {
    asm volatile("cp.async.wait_group %0;" :: "n"(N));
}

// ---------------------------------------------------------------------------
// Tensor-core GEMM: D[32 x 64] tile of Qrows[32,KD] @ Crows[64,KD]^T
//   128 threads = 4 warps as 2(m) x 2(n); warp tile m16 x n32
//   (LDSM/MMA = 0.75: 1 A-LDSM + 2 B-LDSM feed 4 MMAs per k8).
//   S-stage cp.async pipeline (stage = 32 k, 12 KB), inner loop unrolled x S
//   so every stage slot is a compile-time immediate. XOR-swizzled 128B rows.
// LOGITS (S=4, KD=512): A (g_Qp) pre-rounded tf32 -> no cvt on A.
// !LOGITS/qp (S=4, KD=128): cvts both operands; stores tf32-rounded g_Qp;
//   computes g_qb on blockIdx.x==0; fills the rows plane (input-free work).
// ---------------------------------------------------------------------------
template<int KD, int S, bool LOGITS>
__global__ __launch_bounds__(128, 4) void gemm_tc(const float* __restrict__ Qm,
                                                  const float* __restrict__ Cm,
                                                  const float* __restrict__ bv,
                                                  float* __restrict__ out,
                                                  float* __restrict__ rows_out) {
    constexpr int NST  = KD / 32;
    static_assert(NST % S == 0, "NST must be a multiple of S");
    constexpr int OSTR = LOGITS ? CTX_PER : D_MODEL;
    constexpr uint32_t QSTG = 32 * 32 * 4;          // 4 KB per Q stage
    constexpr uint32_t CSTG = 64 * 32 * 4;          // 8 KB per C stage

    __shared__ float Qs[S * 32 * 32];
    __shared__ float Cs[S * 64 * 32];

    const int tid  = threadIdx.x;
    const int lane = tid & 31;
    const int warp = tid >> 5;
    const int wm   = warp >> 1;          // 0..1 (row half)
    const int wn   = warp & 1;           // 0..1 (col half, 32 cols each)
    const int qr   = lane >> 2;
    const int qc   = lane & 3;

    const float* Qbase = LOGITS ? (const float*)g_Qp : Qm;
    const int qrow_base = blockIdx.y * 32;
    const int crow_base = (LOGITS ? blockIdx.y * CTX_PER : 0) + blockIdx.x * 64;
    const int ocol_base = blockIdx.x * 64;

    const uint32_t QsU = s2u(Qs);
    const uint32_t CsU = s2u(Cs);

    // ---- loader: 128 threads; Q: 2 rows each, C: 4 rows each
    const int lrow = tid >> 3;                      // 0..15
    const int lseg = tid & 7;                       // 16B segment
    const int lsw  = (lseg ^ (lrow & 7)) * 16;      // byte offset in row (swz)

    const float* qsrc0 = Qbase + (size_t)(qrow_base + lrow)      * KD + lseg * 4;
    const float* qsrc1 = Qbase + (size_t)(qrow_base + lrow + 16) * KD + lseg * 4;
    const uint32_t qoff0 = (uint32_t)(lrow * 128 + lsw);
    const uint32_t qoff1 = (uint32_t)((lrow + 16) * 128 + lsw);

    const float* csrc[4];
    uint32_t coff[4];
    #pragma unroll
    for (int j = 0; j < 4; j++) {
        int r = lrow + 16 * j;                      // 0..63
        csrc[j] = Cm + (size_t)(crow_base + r) * KD + lseg * 4;
        coff[j] = (uint32_t)(r * 128 + lsw);        // (r&7)==(lrow&7)
    }

    // ---- LDSM per-kk byte offsets
    const int arow  = 16 * wm + (lane & 15);
    const int ahi   = lane >> 4;
    const int amask = arow & 7;
    const int browL = 32 * wn + (lane & 15);
    const int browH = browL + 16;
    const int bmask = browL & 7;                    // == browH & 7
    uint32_t aoff[4], boffL[4], boffH[4];
    #pragma unroll
    for (int kk = 0; kk < 4; kk++) {
        const int ks = ((kk * 2 + ahi) ^ amask) * 16;   // same masks: arow&7
        aoff[kk]  = (uint32_t)(arow * 128 + ((kk * 2 + ahi) ^ amask) * 16);
        boffL[kk] = (uint32_t)(browL * 128 + ((kk * 2 + ahi) ^ bmask) * 16);
        boffH[kk] = (uint32_t)(browH * 128 + ((kk * 2 + ahi) ^ bmask) * 16);
        (void)ks;
    }

    float acc[4][4] = {};                           // [n8-tile 0..3][frag]

    // ---- prologue: stages 0..S-2
    #pragma unroll
    for (int s = 0; s < S - 1; s++) {
        cp16(QsU + s * QSTG + qoff0, qsrc0 + s * 32);
        cp16(QsU + s * QSTG + qoff1, qsrc1 + s * 32);
        #pragma unroll
        for (int j = 0; j < 4; j++)
            cp16(CsU + s * CSTG + coff[j], csrc[j] + s * 32);
        cp_commit();
    }

    // ---- main loop: inner unroll x S -> compile-time stage slots
    #pragma unroll 1
    for (int itS = 0; itS < NST / S; itS++) {
        #pragma unroll
        for (int s = 0; s < S; s++) {
            const int st = itS * S + s;
            cp_wait<S - 2>();
            __syncthreads();

            const uint32_t qstage = QsU + s * QSTG;
            const uint32_t cstage = CsU + s * CSTG;
            #pragma unroll
            for (int kk = 0; kk < 4; kk++) {
                uint32_t a[4], bl[4], bh[4];
                ldsm_x4(a,  qstage + aoff[kk]);
                ldsm_x4(bl, cstage + boffL[kk]);
                ldsm_x4(bh, cstage + boffH[kk]);
                if (!LOGITS) {
                    #pragma unroll
                    for (int u = 0; u < 4; u++) a[u] = bits2tf32(a[u]);
                }
                #pragma unroll
                for (int u = 0; u < 4; u++) { bl[u] = bits2tf32(bl[u]); bh[u] = bits2tf32(bh[u]); }
                mma_tf32(acc[0], a, bl[0], bl[2]);
                mma_tf32(acc[1], a, bl[1], bl[3]);
                mma_tf32(acc[2], a, bh[0], bh[2]);
                mma_tf32(acc[3], a, bh[1], bh[3]);
            }

            if (st + S - 1 < NST) {
                const int nb = (s + S - 1) & (S - 1);   // compile-time slot
                const int ks = (st + S - 1) * 32;
                cp16(QsU + nb * QSTG + qoff0, qsrc0 + ks);
                cp16(QsU + nb * QSTG + qoff1, qsrc1 + ks);
                #pragma unroll
                for (int j = 0; j < 4; j++)
                    cp16(CsU + nb * CSTG + coff[j], csrc[j] + ks);
            }
            cp_commit();
        }
    }

    // ---- epilogue: warp rows [16wm,16wm+16), cols [32wn,32wn+32)
    #pragma unroll
    for (int nt = 0; nt < 4; nt++) {
        #pragma unroll
        for (int half = 0; half < 2; half++) {
            const int rg = qrow_base + 16 * wm + qr + half * 8;
            const int col = ocol_base + 32 * wn + nt * 8 + qc * 2;
            const size_t off = (size_t)rg * OSTR + col;
            float v0 = acc[nt][half * 2 + 0];
            float v1 = acc[nt][half * 2 + 1];
            if (LOGITS) {
                const float qb = g_qb[rg];
                *(float2*)(out + off) = make_float2(v0 + qb, v1 + qb);
            } else {
                *(float2*)(g_Qp + off) =
                    make_float2(__uint_as_float(f2tf32(v0)),
                                __uint_as_float(f2tf32(v1)));
            }
        }
    }

    if (!LOGITS) {
        // rows plane: rows[p] = p >> 10, spread over this kernel's 128 CTAs
        if (rows_out) {
            const int cta = blockIdx.y * gridDim.x + blockIdx.x;  // 0..127
            const int base = cta * 4096;
            float* dst = rows_out + base;
            #pragma unroll
            for (int i = 0; i < 8; i++) {
                int idx = tid * 4 + i * 512;
                float fr = (float)((base + idx) >> 10);
                *(float4*)(dst + idx) = make_float4(fr, fr, fr, fr);
            }
        }
        // fused qb (one column of blocks): 32 rows x 4 segs = 128 threads
        if (blockIdx.x == 0) {
            const int row = qrow_base + (tid >> 2);
            const int seg = tid & 3;
            const float* ap = Qm + (size_t)row * KEY_DIM + seg * 32;
            const float* bp = bv + seg * 32;
            float s = 0.f;
            #pragma unroll
            for (int k = 0; k < 8; k++) {
                float4 a  = *(const float4*)(ap + 4 * k);
                float4 bb = *(const float4*)(bp + 4 * k);
                s = fmaf(a.x, bb.x, s); s = fmaf(a.y, bb.y, s);
                s = fmaf(a.z, bb.z, s); s = fmaf(a.w, bb.w, s);
            }
            s += __shfl_xor_sync(0xffffffffu, s, 1);
            s += __shfl_xor_sync(0xffffffffu, s, 2);
            if (seg == 0) g_qb[row] = s;
        }
    }
}

// ---------------------------------------------------------------------------
extern "C" void kernel_launch(void* const* d_in, const int* in_sizes, int n_in,
                              void* d_out, int out_size) {
    const float* argv = nullptr;
    const float* ctxv = nullptr;
    const float* Wm   = nullptr;
    const float* bv   = nullptr;
    int seen_65536 = 0;
    for (int i = 0; i < n_in; i++) {
        long sz = in_sizes[i];
        if (sz == (long)N_CTX * D_MODEL) {
            ctxv = (const float*)d_in[i];
        } else if (sz == (long)N_ARGS * KEY_DIM) {   // == D_MODEL*KEY_DIM too
            if (seen_65536++ == 0) argv = (const float*)d_in[i];
            else                   Wm   = (const float*)d_in[i];
        } else if (sz == KEY_DIM) {
            bv = (const float*)d_in[i];
        }
    }

    float* out        = (float*)d_out;
    float* rows_out   = nullptr;
    float* logits_out = out;
    if (out_size >= 2 * P_TOT) {        // (rows, logits) concatenated
        rows_out   = out;
        logits_out = out + P_TOT;
    }

    // Qp = arg @ W^T (+ qb + rows plane): K=128, S=4, grid 128 CTAs x 128 thr
    gemm_tc<KEY_DIM, 4, false><<<dim3(8, 16), 128>>>(argv, Wm, bv,
                                                     nullptr, rows_out);

    // logits: [32,1024] per state = Qp_s @ C_s^T + qb: K=512, S=4,
    // grid 256 CTAs x 128 thr
    gemm_tc<D_MODEL, 4, true><<<dim3(16, 16), 128>>>(nullptr, ctxv, nullptr,
                                                     logits_out, nullptr);
}